// round 6
// baseline (speedup 1.0000x reference)
#include <cuda_runtime.h>
#include <cstdint>

#define NB 64       // batch
#define NSLOT 11    // 8 (L1 strips) + 2 (L2 strips) + 1 (L3)
#define NBLK (NB * NSLOT)
#define FINF __int_as_float(0x7f800000)

// Per-(image,slot) exact integer partials [y-sum, x-sum, count] and per-image
// truth-center sums. Every entry rewritten each run -> no init pass needed.
__device__ int   g_part[NB][NSLOT][3];
__device__ float g_tsum[NB][2];
__device__ int   g_ticket;   // zero at load; last block resets to 0 each run

// Load a 6-wide row segment (1 LDG.128 + 2 predicated edge loads) and its
// 4 sliding 3-window maxima. Out-of-range edge neighbors become +INF so
// boundary columns can never be peaks (removes per-pixel validity checks).
template <int W>
__device__ __forceinline__ void load_row(const float* __restrict__ h, int row,
                                         int cg, bool hl, bool hr,
                                         float (&v)[6], float (&hm)[4]) {
    const float* r = h + (size_t)row * W + 4 * cg;
    float4 C = *reinterpret_cast<const float4*>(r);
    v[1] = C.x; v[2] = C.y; v[3] = C.z; v[4] = C.w;
    v[0] = hl ? r[-1] : FINF;
    v[5] = hr ? r[4]  : FINF;
    float p0 = fmaxf(v[0], v[1]), p1 = fmaxf(v[1], v[2]);
    float p2 = fmaxf(v[2], v[3]), p3 = fmaxf(v[3], v[4]);
    hm[0] = fmaxf(p0, v[2]); hm[1] = fmaxf(p1, v[3]);
    hm[2] = fmaxf(p2, v[4]); hm[3] = fmaxf(p3, v[5]);
}

// Thread computes peaks for 4 columns x K rows. Rotating 3-slot row buffer
// (no register shifting); each row's window-max is computed once and reused
// by both center rows that neighbor it.
template <int H, int W, int Rm, int CG, int K>
__device__ __forceinline__ void peak_strip(const float* __restrict__ p, int n,
                                           int base_i, int cg,
                                           int& sy, int& sx, int& cnt) {
    const float* __restrict__ h = p + ((size_t)n * 3 + 2) * (size_t)(H * W);
    const bool hl = (cg > 0), hr = (cg < CG - 1);
    const int jbase = Rm * 4 * cg;

    float v[3][6];
    float hm[3][4];
    load_row<W>(h, base_i > 0 ? base_i - 1 : 0, cg, hl, hr, v[0], hm[0]);
    load_row<W>(h, base_i, cg, hl, hr, v[1], hm[1]);

#pragma unroll
    for (int r = 0; r < K; r++) {
        const int t = r % 3, m = (r + 1) % 3, b = (r + 2) % 3;
        int i = base_i + r;
        int nr = (i + 1 > H - 1) ? H - 1 : i + 1;
        load_row<W>(h, nr, cg, hl, hr, v[b], hm[b]);
        bool rv = (i >= 1) && (i <= H - 2);
#pragma unroll
        for (int k = 0; k < 4; k++) {
            float mx = fmaxf(fmaxf(hm[t][k], hm[b][k]),
                             fmaxf(v[m][k], v[m][k + 2]));
            if (rv && (v[m][k + 1] > mx)) {
                sy += Rm * i;
                sx += jbase + Rm * k;
                cnt++;
            }
        }
    }
}

__device__ __forceinline__ float warp_sum_f(float v) {
#pragma unroll
    for (int o = 16; o; o >>= 1) v += __shfl_xor_sync(0xffffffffu, v, o);
    return v;
}

__global__ void __launch_bounds__(256, 5)
fused_kernel(const float* __restrict__ p1,
             const float* __restrict__ p2,
             const float* __restrict__ p3,
             const float* __restrict__ target,
             float* __restrict__ out) {
    int n = blockIdx.y;
    int slot = blockIdx.x;
    int tid = threadIdx.x;
    int sy = 0, sx = 0, cnt = 0;

    // slot-10 blocks (lightest work) also compute the truth-center sums for
    // their image; loads issued first so they overlap the peak loads.
    if (slot == 10 && tid < 32) {
        const float* t = target + (size_t)n * 32 * 5 + (size_t)tid * 5;
        float v0 = 0.5f * (t[2] + t[0]);
        float v1 = 0.5f * (t[3] + t[1]);
        v0 = warp_sum_f(v0);
        v1 = warp_sum_f(v1);
        if (tid == 0) { g_tsum[n][0] = v0; g_tsum[n][1] = v1; }
    }

    if (slot < 8) {
        // 256x256: 64 col-groups x 4 row-teams; strip = 32 rows, team = 8 rows
        int cg = tid & 63, rt = tid >> 6;
        peak_strip<256, 256, 4, 64, 8>(p1, n, slot * 32 + rt * 8, cg, sy, sx, cnt);
    } else if (slot < 10) {
        // 128x128: 32 col-groups x 8 row-teams; strip = 64 rows, team = 8 rows
        int cg = tid & 31, rt = tid >> 5;
        peak_strip<128, 128, 8, 32, 8>(p2, n, (slot - 8) * 64 + rt * 8, cg, sy, sx, cnt);
    } else {
        // 64x64: 16 col-groups x 16 row-teams; team = 4 rows (covers 64 rows)
        int cg = tid & 15, rt = tid >> 4;
        peak_strip<64, 64, 16, 16, 4>(p3, n, rt * 4, cg, sy, sx, cnt);
    }

    // exact integer block reduction
    sy  = __reduce_add_sync(0xffffffffu, sy);
    sx  = __reduce_add_sync(0xffffffffu, sx);
    cnt = __reduce_add_sync(0xffffffffu, cnt);

    __shared__ int s[3][8];
    __shared__ bool is_last;
    int w = tid >> 5, lane = tid & 31;
    if (lane == 0) { s[0][w] = sy; s[1][w] = sx; s[2][w] = cnt; }
    __syncthreads();
    if (tid == 0) {
        int ty = 0, tx = 0, tc = 0;
#pragma unroll
        for (int k = 0; k < 8; k++) { ty += s[0][k]; tx += s[1][k]; tc += s[2][k]; }
        g_part[n][slot][0] = ty;
        g_part[n][slot][1] = tx;
        g_part[n][slot][2] = tc;
        __threadfence();
        int t = atomicAdd(&g_ticket, 1);
        is_last = (t == NBLK - 1);
    }
    __syncthreads();
    if (!is_last) return;

    // ---- epilogue: the elected last block does the loss ----
    if (tid == 0) g_ticket = 0;   // reset for the next graph replay

    __shared__ float r_offx[2], r_offy[2], r_c0[2], r_c1[2], r_t0[2], r_t1[2];
    __shared__ int r_pc[2];

    if (tid < NB) {
        int cyi = 0, cxi = 0, ci = 0;
#pragma unroll
        for (int sl = 0; sl < NSLOT; sl++) {
            cyi += __ldcg(&g_part[tid][sl][0]);
            cxi += __ldcg(&g_part[tid][sl][1]);
            ci  += __ldcg(&g_part[tid][sl][2]);
        }
        float ts0 = __ldcg(&g_tsum[tid][0]);
        float ts1 = __ldcg(&g_tsum[tid][1]);
        float cy = (float)cyi, cx = (float)cxi;
        float dy = fabsf(cy - ts0);
        float dx = fabsf(cx - ts1);
        float sly = (dy < 1.f) ? 0.5f * dy * dy : dy - 0.5f;
        float slx = (dx < 1.f) ? 0.5f * dx * dx : dx - 0.5f;

        float offx = warp_sum_f(sly);
        float offy = warp_sum_f(slx);
        float c0   = warp_sum_f(cy);
        float c1   = warp_sum_f(cx);
        float t0   = warp_sum_f(ts0);
        float t1   = warp_sum_f(ts1);
        int pc = ci;
#pragma unroll
        for (int o = 16; o; o >>= 1) pc += __shfl_xor_sync(0xffffffffu, pc, o);

        if (lane == 0) {
            r_offx[w] = offx; r_offy[w] = offy;
            r_c0[w] = c0; r_c1[w] = c1; r_t0[w] = t0; r_t1[w] = t1;
            r_pc[w] = pc;
        }
    }
    __syncthreads();
    if (tid == 0) {
        float offx = r_offx[0] + r_offx[1];
        float offy = r_offy[0] + r_offy[1];
        float cst0 = r_c0[0] + r_c0[1];
        float cst1 = r_c1[0] + r_c1[1];
        float tst0 = r_t0[0] + r_t0[1];
        float tst1 = r_t1[0] + r_t1[1];
        int pc = r_pc[0] + r_pc[1];
        float sgx = offx / fabsf(offx);
        float sgy = offy / fabsf(offy);
        out[0] = (sgx * (cst0 - tst0) + sgy * (cst1 - tst1)) / (float)pc;
    }
}

extern "C" void kernel_launch(void* const* d_in, const int* in_sizes, int n_in,
                              void* d_out, int out_size) {
    const float* p1  = (const float*)d_in[0];
    const float* p2  = (const float*)d_in[1];
    const float* p3  = (const float*)d_in[2];
    const float* tgt = (const float*)d_in[3];
    float* out = (float*)d_out;

    dim3 grid(NSLOT, NB);
    fused_kernel<<<grid, 256>>>(p1, p2, p3, tgt, out);
}

// round 8
// speedup vs baseline: 1.0021x; 1.0021x over previous
#include <cuda_runtime.h>
#include <cstdint>

#define NB 64       // batch
#define NSLOT 11    // 8 (L1 strips) + 2 (L2 strips) + 1 (L3)
#define NBLK (NB * NSLOT)
#define FINF __int_as_float(0x7f800000)

// Per-(image,slot) exact integer partials [y-sum, x-sum, count] and per-image
// truth-center sums. Every entry rewritten each run -> no init pass needed.
__device__ int   g_part[NB][NSLOT][3];
__device__ float g_tsum[NB][2];
__device__ int   g_ticket;   // zero at load; last block resets to 0 each run

// Load a 6-wide row segment: ONE LDG.128 for the 4 own columns; the two edge
// neighbors come from adjacent lanes via shfl (lanes hold consecutive col
// groups). Only segment-boundary lanes do a real (predicated, single-lane)
// edge load; out-of-image neighbors become +INF so boundary columns can never
// be peaks. Also computes the 4 sliding 3-window maxima for this row.
template <int W, int CG, int SEG>
__device__ __forceinline__ void load_row(const float* __restrict__ h, int row,
                                         int cg, float (&v)[6], float (&hm)[4]) {
    const float* r = h + (size_t)row * W + 4 * cg;
    float4 C = *reinterpret_cast<const float4*>(r);
    float lw = __shfl_up_sync(0xffffffffu, C.w, 1, SEG);
    float rx = __shfl_down_sync(0xffffffffu, C.x, 1, SEG);
    const int ls = cg & (SEG - 1);
    if (ls == 0)       lw = (cg > 0)      ? r[-1] : FINF;
    if (ls == SEG - 1) rx = (cg < CG - 1) ? r[4]  : FINF;
    v[0] = lw; v[1] = C.x; v[2] = C.y; v[3] = C.z; v[4] = C.w; v[5] = rx;
    float p0 = fmaxf(v[0], v[1]), p1 = fmaxf(v[1], v[2]);
    float p2 = fmaxf(v[2], v[3]), p3 = fmaxf(v[3], v[4]);
    hm[0] = fmaxf(p0, v[2]); hm[1] = fmaxf(p1, v[3]);
    hm[2] = fmaxf(p2, v[4]); hm[3] = fmaxf(p3, v[5]);
}

// Thread computes peaks for 4 columns x K rows. Prefetch distance 2:
// while computing centers of row r, loads of rows r+1 AND r+2 are in flight.
// v rotates over 3 slots (rows r..r+2 live), hm over 4 (rows r-1..r+2 live).
template <int H, int W, int Rm, int CG, int SEG, int K>
__device__ __forceinline__ void peak_strip(const float* __restrict__ p, int n,
                                           int base_i, int cg,
                                           int& sy, int& sx, int& cnt) {
    const float* __restrict__ h = p + ((size_t)n * 3 + 2) * (size_t)(H * W);
    const int jbase = Rm * 4 * cg;

    float v[3][6];
    float hm[4][4];
    // logical row q stored in v[(q+1)%3], hm[(q+1)%4]
    load_row<W, CG, SEG>(h, base_i > 0 ? base_i - 1 : 0, cg, v[0], hm[0]); // q=-1
    load_row<W, CG, SEG>(h, base_i, cg, v[1], hm[1]);                      // q=0
    {
        int r1 = base_i + 1; if (r1 > H - 1) r1 = H - 1;
        load_row<W, CG, SEG>(h, r1, cg, v[2], hm[2]);                      // q=1
    }

#pragma unroll
    for (int r = 0; r < K; r++) {
        if (r + 2 <= K) {   // prefetch row r+2 (compile-time guard)
            int nr = base_i + r + 2; if (nr > H - 1) nr = H - 1;
            load_row<W, CG, SEG>(h, nr, cg, v[(r + 3) % 3], hm[(r + 3) % 4]);
        }
        const int t4 = r % 4, b4 = (r + 2) % 4, m3 = (r + 1) % 3;
        int i = base_i + r;
        bool rv = (i >= 1) && (i <= H - 2);
#pragma unroll
        for (int k = 0; k < 4; k++) {
            float mx = fmaxf(fmaxf(hm[t4][k], hm[b4][k]),
                             fmaxf(v[m3][k], v[m3][k + 2]));
            if (rv && (v[m3][k + 1] > mx)) {
                sy += Rm * i;
                sx += jbase + Rm * k;
                cnt++;
            }
        }
    }
}

__device__ __forceinline__ float warp_sum_f(float v) {
#pragma unroll
    for (int o = 16; o; o >>= 1) v += __shfl_xor_sync(0xffffffffu, v, o);
    return v;
}

__global__ void __launch_bounds__(256, 5)
fused_kernel(const float* __restrict__ p1,
             const float* __restrict__ p2,
             const float* __restrict__ p3,
             const float* __restrict__ target,
             float* __restrict__ out) {
    int n = blockIdx.y;
    int slot = blockIdx.x;
    int tid = threadIdx.x;
    int sy = 0, sx = 0, cnt = 0;

    // slot-10 blocks (lightest work) also compute the truth-center sums for
    // their image; loads issued first so they overlap the peak loads.
    if (slot == 10 && tid < 32) {
        const float* t = target + (size_t)n * 32 * 5 + (size_t)tid * 5;
        float v0 = 0.5f * (t[2] + t[0]);
        float v1 = 0.5f * (t[3] + t[1]);
        v0 = warp_sum_f(v0);
        v1 = warp_sum_f(v1);
        if (tid == 0) { g_tsum[n][0] = v0; g_tsum[n][1] = v1; }
    }

    if (slot < 8) {
        // 256x256: 64 col-groups x 4 row-teams; strip = 32 rows, team = 8 rows
        int cg = tid & 63, rt = tid >> 6;
        peak_strip<256, 256, 4, 64, 32, 8>(p1, n, slot * 32 + rt * 8, cg, sy, sx, cnt);
    } else if (slot < 10) {
        // 128x128: 32 col-groups x 8 row-teams; strip = 64 rows, team = 8 rows
        int cg = tid & 31, rt = tid >> 5;
        peak_strip<128, 128, 8, 32, 32, 8>(p2, n, (slot - 8) * 64 + rt * 8, cg, sy, sx, cnt);
    } else {
        // 64x64: 16 col-groups x 16 row-teams; team = 4 rows (covers 64 rows)
        int cg = tid & 15, rt = tid >> 4;
        peak_strip<64, 64, 16, 16, 16, 4>(p3, n, rt * 4, cg, sy, sx, cnt);
    }

    // exact integer block reduction
    sy  = __reduce_add_sync(0xffffffffu, sy);
    sx  = __reduce_add_sync(0xffffffffu, sx);
    cnt = __reduce_add_sync(0xffffffffu, cnt);

    __shared__ int s[3][8];
    __shared__ bool is_last;
    int w = tid >> 5, lane = tid & 31;
    if (lane == 0) { s[0][w] = sy; s[1][w] = sx; s[2][w] = cnt; }
    __syncthreads();
    if (tid == 0) {
        int ty = 0, tx = 0, tc = 0;
#pragma unroll
        for (int k = 0; k < 8; k++) { ty += s[0][k]; tx += s[1][k]; tc += s[2][k]; }
        g_part[n][slot][0] = ty;
        g_part[n][slot][1] = tx;
        g_part[n][slot][2] = tc;
        __threadfence();
        int t = atomicAdd(&g_ticket, 1);
        is_last = (t == NBLK - 1);
    }
    __syncthreads();
    if (!is_last) return;

    // ---- epilogue: the elected last block does the loss ----
    if (tid == 0) g_ticket = 0;   // reset for the next graph replay

    __shared__ float r_offx[2], r_offy[2], r_c0[2], r_c1[2], r_t0[2], r_t1[2];
    __shared__ int r_pc[2];

    if (tid < NB) {
        int cyi = 0, cxi = 0, ci = 0;
#pragma unroll
        for (int sl = 0; sl < NSLOT; sl++) {
            cyi += __ldcg(&g_part[tid][sl][0]);
            cxi += __ldcg(&g_part[tid][sl][1]);
            ci  += __ldcg(&g_part[tid][sl][2]);
        }
        float ts0 = __ldcg(&g_tsum[tid][0]);
        float ts1 = __ldcg(&g_tsum[tid][1]);
        float cy = (float)cyi, cx = (float)cxi;
        float dy = fabsf(cy - ts0);
        float dx = fabsf(cx - ts1);
        float sly = (dy < 1.f) ? 0.5f * dy * dy : dy - 0.5f;
        float slx = (dx < 1.f) ? 0.5f * dx * dx : dx - 0.5f;

        float offx = warp_sum_f(sly);
        float offy = warp_sum_f(slx);
        float c0   = warp_sum_f(cy);
        float c1   = warp_sum_f(cx);
        float t0   = warp_sum_f(ts0);
        float t1   = warp_sum_f(ts1);
        int pc = ci;
#pragma unroll
        for (int o = 16; o; o >>= 1) pc += __shfl_xor_sync(0xffffffffu, pc, o);

        if (lane == 0) {
            r_offx[w] = offx; r_offy[w] = offy;
            r_c0[w] = c0; r_c1[w] = c1; r_t0[w] = t0; r_t1[w] = t1;
            r_pc[w] = pc;
        }
    }
    __syncthreads();
    if (tid == 0) {
        float offx = r_offx[0] + r_offx[1];
        float offy = r_offy[0] + r_offy[1];
        float cst0 = r_c0[0] + r_c0[1];
        float cst1 = r_c1[0] + r_c1[1];
        float tst0 = r_t0[0] + r_t0[1];
        float tst1 = r_t1[0] + r_t1[1];
        int pc = r_pc[0] + r_pc[1];
        float sgx = offx / fabsf(offx);
        float sgy = offy / fabsf(offy);
        out[0] = (sgx * (cst0 - tst0) + sgy * (cst1 - tst1)) / (float)pc;
    }
}

extern "C" void kernel_launch(void* const* d_in, const int* in_sizes, int n_in,
                              void* d_out, int out_size) {
    const float* p1  = (const float*)d_in[0];
    const float* p2  = (const float*)d_in[1];
    const float* p3  = (const float*)d_in[2];
    const float* tgt = (const float*)d_in[3];
    float* out = (float*)d_out;

    dim3 grid(NSLOT, NB);
    fused_kernel<<<grid, 256>>>(p1, p2, p3, tgt, out);
}

// round 10
// speedup vs baseline: 1.2228x; 1.2202x over previous
#include <cuda_runtime.h>
#include <cstdint>

#define NB 64       // batch
#define NSLOT 11    // 8 (L1 strips) + 2 (L2 strips) + 1 (L3)
#define NBLK (NB * NSLOT)
#define FINF __int_as_float(0x7f800000)

// Per-(image,slot) exact integer partials [y-sum, x-sum, count] and per-image
// truth-center sums. Every entry rewritten each run -> no init pass needed.
__device__ int   g_part[NB][NSLOT][3];
__device__ float g_tsum[NB][2];
__device__ int   g_ticket;   // zero at load; last block resets to 0 each run

// Raw row-segment load only: 1 LDG.128 + 2 predicated per-lane edge loads.
// NO dependent compute here -- consumption is deferred a full iteration so
// the loads stay in flight (true software pipelining).
template <int W, int CG>
__device__ __forceinline__ void load_row_raw(const float* __restrict__ h, int row,
                                             int cg, bool hl, bool hr,
                                             float (&v)[6]) {
    const float* r = h + (size_t)row * W + 4 * cg;
    float4 C = *reinterpret_cast<const float4*>(r);
    v[1] = C.x; v[2] = C.y; v[3] = C.z; v[4] = C.w;
    v[0] = hl ? r[-1] : FINF;
    v[5] = hr ? r[4]  : FINF;
}

// Sliding 3-window horizontal maxima for a loaded row.
__device__ __forceinline__ void calc_hm(const float (&v)[6], float (&hm)[4]) {
    float p0 = fmaxf(v[0], v[1]), p1 = fmaxf(v[1], v[2]);
    float p2 = fmaxf(v[2], v[3]), p3 = fmaxf(v[3], v[4]);
    hm[0] = fmaxf(p0, v[2]); hm[1] = fmaxf(p1, v[3]);
    hm[2] = fmaxf(p2, v[4]); hm[3] = fmaxf(p3, v[5]);
}

// Thread computes peaks for 4 columns x K rows. Decoupled pipeline:
//   iter r: issue raw load of logical row r+3   (used at iter r+2)
//           compute hm of logical row r+2        (loaded at iter r-1)
//           peak-test center = logical row r+1.
// Logical row q (global row base_i+q-1) lives in v[q%3] / hm[q%3]; the slot
// overwritten by the new load is the top row, whose raw v is dead (hm kept).
template <int H, int W, int Rm, int CG, int K>
__device__ __forceinline__ void peak_strip(const float* __restrict__ p, int n,
                                           int base_i, int cg,
                                           int& sy, int& sx, int& cnt) {
    const float* __restrict__ h = p + ((size_t)n * 3 + 2) * (size_t)(H * W);
    const bool hl = (cg > 0), hr = (cg < CG - 1);
    const int jbase = Rm * 4 * cg;

    float v[3][6];
    float hm[3][4];
    // prologue: logical rows 0,1,2 = global base_i-1, base_i, base_i+1
    load_row_raw<W, CG>(h, base_i > 0 ? base_i - 1 : 0, cg, hl, hr, v[0]);
    load_row_raw<W, CG>(h, base_i, cg, hl, hr, v[1]);
    {
        int r1 = base_i + 1; if (r1 > H - 1) r1 = H - 1;
        load_row_raw<W, CG>(h, r1, cg, hl, hr, v[2]);
    }
    calc_hm(v[0], hm[0]);
    calc_hm(v[1], hm[1]);

#pragma unroll
    for (int r = 0; r < K; r++) {
        if (r <= K - 2) {   // issue load of logical row r+3 (global i+2)
            int nr = base_i + r + 2; if (nr > H - 1) nr = H - 1;
            load_row_raw<W, CG>(h, nr, cg, hl, hr, v[r % 3]);
        }
        const int mid = (r + 1) % 3, bot = (r + 2) % 3, top = r % 3;
        calc_hm(v[bot], hm[bot]);   // row loaded one full iteration ago
        int i = base_i + r;
        bool rv = (i >= 1) && (i <= H - 2);
#pragma unroll
        for (int k = 0; k < 4; k++) {
            float mx = fmaxf(fmaxf(hm[top][k], hm[bot][k]),
                             fmaxf(v[mid][k], v[mid][k + 2]));
            if (rv && (v[mid][k + 1] > mx)) {
                sy += Rm * i;
                sx += jbase + Rm * k;
                cnt++;
            }
        }
    }
}

__device__ __forceinline__ float warp_sum_f(float v) {
#pragma unroll
    for (int o = 16; o; o >>= 1) v += __shfl_xor_sync(0xffffffffu, v, o);
    return v;
}

__global__ void __launch_bounds__(256, 5)
fused_kernel(const float* __restrict__ p1,
             const float* __restrict__ p2,
             const float* __restrict__ p3,
             const float* __restrict__ target,
             float* __restrict__ out) {
    int n = blockIdx.y;
    int slot = blockIdx.x;
    int tid = threadIdx.x;
    int sy = 0, sx = 0, cnt = 0;

    // slot-10 blocks (lightest work) also compute the truth-center sums for
    // their image; loads issued first so they overlap the peak loads.
    if (slot == 10 && tid < 32) {
        const float* t = target + (size_t)n * 32 * 5 + (size_t)tid * 5;
        float v0 = 0.5f * (t[2] + t[0]);
        float v1 = 0.5f * (t[3] + t[1]);
        v0 = warp_sum_f(v0);
        v1 = warp_sum_f(v1);
        if (tid == 0) { g_tsum[n][0] = v0; g_tsum[n][1] = v1; }
    }

    if (slot < 8) {
        // 256x256: 64 col-groups x 4 row-teams; strip = 32 rows, team = 8 rows
        int cg = tid & 63, rt = tid >> 6;
        peak_strip<256, 256, 4, 64, 8>(p1, n, slot * 32 + rt * 8, cg, sy, sx, cnt);
    } else if (slot < 10) {
        // 128x128: 32 col-groups x 8 row-teams; strip = 64 rows, team = 8 rows
        int cg = tid & 31, rt = tid >> 5;
        peak_strip<128, 128, 8, 32, 8>(p2, n, (slot - 8) * 64 + rt * 8, cg, sy, sx, cnt);
    } else {
        // 64x64: 16 col-groups x 16 row-teams; team = 4 rows (covers 64 rows)
        int cg = tid & 15, rt = tid >> 4;
        peak_strip<64, 64, 16, 16, 4>(p3, n, rt * 4, cg, sy, sx, cnt);
    }

    // exact integer block reduction
    sy  = __reduce_add_sync(0xffffffffu, sy);
    sx  = __reduce_add_sync(0xffffffffu, sx);
    cnt = __reduce_add_sync(0xffffffffu, cnt);

    __shared__ int s[3][8];
    __shared__ bool is_last;
    int w = tid >> 5, lane = tid & 31;
    if (lane == 0) { s[0][w] = sy; s[1][w] = sx; s[2][w] = cnt; }
    __syncthreads();
    if (tid == 0) {
        int ty = 0, tx = 0, tc = 0;
#pragma unroll
        for (int k = 0; k < 8; k++) { ty += s[0][k]; tx += s[1][k]; tc += s[2][k]; }
        g_part[n][slot][0] = ty;
        g_part[n][slot][1] = tx;
        g_part[n][slot][2] = tc;
        __threadfence();
        int t = atomicAdd(&g_ticket, 1);
        is_last = (t == NBLK - 1);
    }
    __syncthreads();
    if (!is_last) return;

    // ---- epilogue: the elected last block does the loss ----
    if (tid == 0) g_ticket = 0;   // reset for the next graph replay

    __shared__ float r_offx[2], r_offy[2], r_c0[2], r_c1[2], r_t0[2], r_t1[2];
    __shared__ int r_pc[2];

    if (tid < NB) {
        int cyi = 0, cxi = 0, ci = 0;
#pragma unroll
        for (int sl = 0; sl < NSLOT; sl++) {
            cyi += __ldcg(&g_part[tid][sl][0]);
            cxi += __ldcg(&g_part[tid][sl][1]);
            ci  += __ldcg(&g_part[tid][sl][2]);
        }
        float ts0 = __ldcg(&g_tsum[tid][0]);
        float ts1 = __ldcg(&g_tsum[tid][1]);
        float cy = (float)cyi, cx = (float)cxi;
        float dy = fabsf(cy - ts0);
        float dx = fabsf(cx - ts1);
        float sly = (dy < 1.f) ? 0.5f * dy * dy : dy - 0.5f;
        float slx = (dx < 1.f) ? 0.5f * dx * dx : dx - 0.5f;

        float offx = warp_sum_f(sly);
        float offy = warp_sum_f(slx);
        float c0   = warp_sum_f(cy);
        float c1   = warp_sum_f(cx);
        float t0   = warp_sum_f(ts0);
        float t1   = warp_sum_f(ts1);
        int pc = ci;
#pragma unroll
        for (int o = 16; o; o >>= 1) pc += __shfl_xor_sync(0xffffffffu, pc, o);

        if (lane == 0) {
            r_offx[w] = offx; r_offy[w] = offy;
            r_c0[w] = c0; r_c1[w] = c1; r_t0[w] = t0; r_t1[w] = t1;
            r_pc[w] = pc;
        }
    }
    __syncthreads();
    if (tid == 0) {
        float offx = r_offx[0] + r_offx[1];
        float offy = r_offy[0] + r_offy[1];
        float cst0 = r_c0[0] + r_c0[1];
        float cst1 = r_c1[0] + r_c1[1];
        float tst0 = r_t0[0] + r_t0[1];
        float tst1 = r_t1[0] + r_t1[1];
        int pc = r_pc[0] + r_pc[1];
        float sgx = offx / fabsf(offx);
        float sgy = offy / fabsf(offy);
        out[0] = (sgx * (cst0 - tst0) + sgy * (cst1 - tst1)) / (float)pc;
    }
}

extern "C" void kernel_launch(void* const* d_in, const int* in_sizes, int n_in,
                              void* d_out, int out_size) {
    const float* p1  = (const float*)d_in[0];
    const float* p2  = (const float*)d_in[1];
    const float* p3  = (const float*)d_in[2];
    const float* tgt = (const float*)d_in[3];
    float* out = (float*)d_out;

    dim3 grid(NSLOT, NB);
    fused_kernel<<<grid, 256>>>(p1, p2, p3, tgt, out);
}